// round 1
// baseline (speedup 1.0000x reference)
#include <cuda_runtime.h>
#include <math.h>

// ---------------------------------------------------------------------------
// MinGPT forward, fp32 baseline.  B=4, S=1024, D=1024, H=16, HS=64, L=4,
// DFF=4096, V=32000.  All GEMM dims divide the 128x128x16 tile exactly.
// ---------------------------------------------------------------------------

#define B_  4
#define S_  1024
#define D_  1024
#define H_  16
#define HS_ 64
#define L_  4
#define DFF_ 4096
#define V_  32000
#define M_  (B_ * S_)          // 4096 rows of activations
#define EPS_ 1e-5f
#define SCALE_ 0.03125f        // D^-0.5 = 1/32  (reference uses d_model, not head_size)

// ------------------------- scratch (static device arrays; no allocs) -------
__device__ float g_x  [M_ * D_];
__device__ float g_xn [M_ * D_];
__device__ float g_q  [M_ * D_];
__device__ float g_k  [M_ * D_];
__device__ float g_v  [M_ * D_];
__device__ float g_att[M_ * D_];
__device__ float g_h  [M_ * DFF_];

// ------------------------- embedding ---------------------------------------
// one block per token row, one float4 per thread (256*4 = 1024 = D)
__global__ __launch_bounds__(256) void embed_k(
    const int* __restrict__ idx, const float4* __restrict__ tok,
    const float4* __restrict__ pos, float4* __restrict__ x)
{
    int row = blockIdx.x;                 // b*S + s
    int s   = row & (S_ - 1);
    int t   = idx[row];
    int c   = threadIdx.x;                // 0..255 float4 chunks
    float4 tv = tok[(size_t)t * (D_ / 4) + c];
    float4 pv = pos[(size_t)s * (D_ / 4) + c];
    float4 o;
    o.x = tv.x + pv.x; o.y = tv.y + pv.y; o.z = tv.z + pv.z; o.w = tv.w + pv.w;
    x[(size_t)row * (D_ / 4) + c] = o;
}

// ------------------------- layer norm --------------------------------------
// one block per row; each thread owns exactly one float4 of the 1024-wide row
__global__ __launch_bounds__(256) void layernorm_k(
    const float4* __restrict__ x, const float4* __restrict__ g,
    const float4* __restrict__ bb, float4* __restrict__ y)
{
    int row = blockIdx.x;
    int tid = threadIdx.x;
    __shared__ float red[256];

    float4 xv = x[(size_t)row * 256 + tid];

    float s = xv.x + xv.y + xv.z + xv.w;
    red[tid] = s; __syncthreads();
    #pragma unroll
    for (int st = 128; st > 0; st >>= 1) {
        if (tid < st) red[tid] += red[tid + st];
        __syncthreads();
    }
    float mu = red[0] * (1.0f / D_);
    __syncthreads();

    float dx = xv.x - mu, dy = xv.y - mu, dz = xv.z - mu, dw = xv.w - mu;
    float s2 = dx * dx + dy * dy + dz * dz + dw * dw;
    red[tid] = s2; __syncthreads();
    #pragma unroll
    for (int st = 128; st > 0; st >>= 1) {
        if (tid < st) red[tid] += red[tid + st];
        __syncthreads();
    }
    float var = red[0] * (1.0f / D_);
    float inv = rsqrtf(var + EPS_);

    float4 gv = g[tid], bv = bb[tid];
    float4 o;
    o.x = dx * inv * gv.x + bv.x;
    o.y = dy * inv * gv.y + bv.y;
    o.z = dz * inv * gv.z + bv.z;
    o.w = dw * inv * gv.w + bv.w;
    y[(size_t)row * 256 + tid] = o;
}

// ------------------------- SGEMM  C[M,N] = A[M,K] @ B[K,N] (+bias)(+res)(relu)
// 128x128 block tile, BK=16, 8x8 per thread, 256 threads.
template<bool BIAS, bool RES, bool RELU>
__global__ __launch_bounds__(256) void sgemm_k(
    int M, int N, int K,
    const float* __restrict__ A, const float* __restrict__ B,
    const float* __restrict__ bias, const float* __restrict__ res,
    float* __restrict__ C)
{
    const int BM = 128, BN = 128, BK = 16, TM = 8, TN = 8;
    __shared__ float As[BK][BM + 4];   // +4 pad breaks store-phase conflicts
    __shared__ float Bs[BK][BN];

    int tid = threadIdx.x;
    int cRow = blockIdx.y, cCol = blockIdx.x;

    int threadCol = tid % (BN / TN);   // 0..15
    int threadRow = tid / (BN / TN);   // 0..15

    const float* Ap = A + (size_t)cRow * BM * K;
    const float* Bp = B + (size_t)cCol * BN;
    float*       Cp = C + (size_t)cRow * BM * N + (size_t)cCol * BN;
    const float* Rp = RES  ? res  + (size_t)cRow * BM * N + (size_t)cCol * BN : nullptr;
    const float* bp = BIAS ? bias + (size_t)cCol * BN : nullptr;

    int innerRowA = tid / 4;           // 0..63  (2 passes of 64 rows)
    int innerColA = tid % 4;           // *4 floats over BK=16
    int innerRowB = tid / 32;          // 0..7   (2 passes of 8 rows)
    int innerColB = tid % 32;          // *4 floats over BN=128

    float acc[TM][TN];
    #pragma unroll
    for (int i = 0; i < TM; i++)
        #pragma unroll
        for (int j = 0; j < TN; j++) acc[i][j] = 0.0f;

    float regM[TM], regN[TN];

    for (int k0 = 0; k0 < K; k0 += BK) {
        #pragma unroll
        for (int off = 0; off < BM; off += 64) {
            float4 t = *(const float4*)(Ap + (size_t)(innerRowA + off) * K + innerColA * 4);
            As[innerColA * 4 + 0][innerRowA + off] = t.x;
            As[innerColA * 4 + 1][innerRowA + off] = t.y;
            As[innerColA * 4 + 2][innerRowA + off] = t.z;
            As[innerColA * 4 + 3][innerRowA + off] = t.w;
        }
        #pragma unroll
        for (int off = 0; off < BK; off += 8) {
            *(float4*)(&Bs[innerRowB + off][innerColB * 4]) =
                *(const float4*)(Bp + (size_t)(innerRowB + off) * N + innerColB * 4);
        }
        __syncthreads();
        Ap += BK;
        Bp += (size_t)BK * N;

        #pragma unroll
        for (int k = 0; k < BK; k++) {
            #pragma unroll
            for (int i = 0; i < TM; i++) regM[i] = As[k][threadRow * TM + i];
            #pragma unroll
            for (int j = 0; j < TN; j++) regN[j] = Bs[k][threadCol * TN + j];
            #pragma unroll
            for (int i = 0; i < TM; i++)
                #pragma unroll
                for (int j = 0; j < TN; j++)
                    acc[i][j] += regM[i] * regN[j];
        }
        __syncthreads();
    }

    #pragma unroll
    for (int i = 0; i < TM; i++) {
        int r = threadRow * TM + i;
        #pragma unroll
        for (int j = 0; j < TN; j += 4) {
            int c = threadCol * TN + j;
            float4 o;
            o.x = acc[i][j + 0]; o.y = acc[i][j + 1];
            o.z = acc[i][j + 2]; o.w = acc[i][j + 3];
            if (BIAS) {
                o.x += bp[c + 0]; o.y += bp[c + 1];
                o.z += bp[c + 2]; o.w += bp[c + 3];
            }
            if (RES) {
                float4 rv = *(const float4*)(Rp + (size_t)r * N + c);
                o.x += rv.x; o.y += rv.y; o.z += rv.z; o.w += rv.w;
            }
            if (RELU) {
                o.x = fmaxf(o.x, 0.0f); o.y = fmaxf(o.y, 0.0f);
                o.z = fmaxf(o.z, 0.0f); o.w = fmaxf(o.w, 0.0f);
            }
            *(float4*)(Cp + (size_t)r * N + c) = o;
        }
    }
}

// ------------------------- causal attention ---------------------------------
// one block (128 threads) per (query, head, batch).  K/V live in L2 (16 MB).
__global__ __launch_bounds__(128) void attention_k(
    const float* __restrict__ q, const float* __restrict__ k,
    const float* __restrict__ v, float* __restrict__ o)
{
    int qi = blockIdx.x, h = blockIdx.y, b = blockIdx.z;
    int tid = threadIdx.x;
    int n = qi + 1;                       // causal: keys 0..qi

    __shared__ float sc[S_];
    __shared__ float qv[HS_];
    __shared__ float red[128];

    const float* qp = q + (((size_t)b * S_ + qi) * H_ + h) * HS_;
    if (tid < HS_) qv[tid] = qp[tid];
    __syncthreads();

    // scores + running max
    float lmax = -1e30f;
    for (int j = tid; j < n; j += 128) {
        const float* kp = k + (((size_t)b * S_ + j) * H_ + h) * HS_;
        float dot = 0.0f;
        #pragma unroll
        for (int d = 0; d < HS_; d += 4) {
            float4 kk = *(const float4*)(kp + d);
            dot += kk.x * qv[d] + kk.y * qv[d + 1] + kk.z * qv[d + 2] + kk.w * qv[d + 3];
        }
        dot *= SCALE_;
        sc[j] = dot;
        lmax = fmaxf(lmax, dot);
    }
    red[tid] = lmax; __syncthreads();
    #pragma unroll
    for (int st = 64; st > 0; st >>= 1) {
        if (tid < st) red[tid] = fmaxf(red[tid], red[tid + st]);
        __syncthreads();
    }
    float m = red[0];
    __syncthreads();

    // exp + sum
    float lsum = 0.0f;
    for (int j = tid; j < n; j += 128) {
        float e = __expf(sc[j] - m);
        sc[j] = e;
        lsum += e;
    }
    red[tid] = lsum; __syncthreads();
    #pragma unroll
    for (int st = 64; st > 0; st >>= 1) {
        if (tid < st) red[tid] += red[tid + st];
        __syncthreads();
    }
    float inv = 1.0f / red[0];
    __syncthreads();

    // out[d] = sum_j p_j * v[j,d] ; 128 threads = 2 j-halves x 64 dims (coalesced)
    int d    = tid & (HS_ - 1);
    int half = tid >> 6;
    float accv = 0.0f;
    for (int j = half; j < n; j += 2)
        accv += sc[j] * v[(((size_t)b * S_ + j) * H_ + h) * HS_ + d];
    red[tid] = accv; __syncthreads();
    if (half == 0)
        o[(((size_t)b * S_ + qi) * H_ + h) * HS_ + d] = (red[tid] + red[tid + 64]) * inv;
}

// ------------------------- driver -------------------------------------------
extern "C" void kernel_launch(void* const* d_in, const int* in_sizes, int n_in,
                              void* d_out, int out_size)
{
    const int*   idx   = (const int*)  d_in[0];
    const float* tok   = (const float*)d_in[1];
    const float* pos   = (const float*)d_in[2];
    const float* ln1g  = (const float*)d_in[3];
    const float* ln1b  = (const float*)d_in[4];
    const float* ln2g  = (const float*)d_in[5];
    const float* ln2b  = (const float*)d_in[6];
    const float* wq    = (const float*)d_in[7];
    const float* wk    = (const float*)d_in[8];
    const float* wv    = (const float*)d_in[9];
    const float* wo    = (const float*)d_in[10];
    const float* bo    = (const float*)d_in[11];
    const float* w1    = (const float*)d_in[12];
    const float* b1    = (const float*)d_in[13];
    const float* w2    = (const float*)d_in[14];
    const float* b2    = (const float*)d_in[15];
    const float* lnfg  = (const float*)d_in[16];
    const float* lnfb  = (const float*)d_in[17];
    const float* whead = (const float*)d_in[18];
    const float* bhead = (const float*)d_in[19];
    float* out = (float*)d_out;

    float *x, *xn, *q, *k, *v, *att, *hb;
    cudaGetSymbolAddress((void**)&x,   g_x);
    cudaGetSymbolAddress((void**)&xn,  g_xn);
    cudaGetSymbolAddress((void**)&q,   g_q);
    cudaGetSymbolAddress((void**)&k,   g_k);
    cudaGetSymbolAddress((void**)&v,   g_v);
    cudaGetSymbolAddress((void**)&att, g_att);
    cudaGetSymbolAddress((void**)&hb,  g_h);

    dim3 blk(256);
    embed_k<<<M_, blk>>>(idx, (const float4*)tok, (const float4*)pos, (float4*)x);

    for (int l = 0; l < L_; l++) {
        layernorm_k<<<M_, blk>>>((const float4*)x, (const float4*)(ln1g + l * D_),
                                 (const float4*)(ln1b + l * D_), (float4*)xn);

        dim3 gQ(D_ / 128, M_ / 128);   // (8,32)
        sgemm_k<false,false,false><<<gQ, blk>>>(M_, D_, D_, xn, wq + (size_t)l*D_*D_, nullptr, nullptr, q);
        sgemm_k<false,false,false><<<gQ, blk>>>(M_, D_, D_, xn, wk + (size_t)l*D_*D_, nullptr, nullptr, k);
        sgemm_k<false,false,false><<<gQ, blk>>>(M_, D_, D_, xn, wv + (size_t)l*D_*D_, nullptr, nullptr, v);

        attention_k<<<dim3(S_, H_, B_), 128>>>(q, k, v, att);

        // x = xn + att @ wo + bo
        sgemm_k<true,true,false><<<gQ, blk>>>(M_, D_, D_, att, wo + (size_t)l*D_*D_,
                                              bo + l * D_, xn, x);

        layernorm_k<<<M_, blk>>>((const float4*)x, (const float4*)(ln2g + l * D_),
                                 (const float4*)(ln2b + l * D_), (float4*)xn);

        // h = relu(xn @ w1 + b1)
        sgemm_k<true,false,true><<<dim3(DFF_/128, M_/128), blk>>>(
            M_, DFF_, D_, xn, w1 + (size_t)l*D_*DFF_, b1 + l * DFF_, nullptr, hb);

        // x = xn + h @ w2 + b2
        sgemm_k<true,true,false><<<dim3(D_/128, M_/128), blk>>>(
            M_, D_, DFF_, hb, w2 + (size_t)l*DFF_*D_, b2 + l * D_, xn, x);
    }

    layernorm_k<<<M_, blk>>>((const float4*)x, (const float4*)lnfg,
                             (const float4*)lnfb, (float4*)xn);

    // logits = xn @ w_head + b_head   -> d_out [4096, 32000]
    sgemm_k<true,false,false><<<dim3(V_/128, M_/128), blk>>>(
        M_, V_, D_, xn, whead, bhead, nullptr, out);
}